// round 11
// baseline (speedup 1.0000x reference)
#include <cuda_runtime.h>

#define FEATURES   2048
#define SCALE      4.0f
#define TPB        256
#define UNROLL     8
#define PER_BLOCK  (TPB * UNROLL)   // 2048 float4 = 4 rows of FEATURES

// out = sigmoid(SCALE * (x * w[f] + b[f])) over [32768, 2048] fp32. HBM-bound.
//
// Exact-cover fast path: PER_BLOCK (2048) is a multiple of FEATURES/4 (512),
// so fi = idx & 511 depends only on (tid, u&1): fi = tid + (u&1)*256.
// => hoist w/b to 2 register-resident float4 pairs, SCALE pre-folded.
// 8 independent front-batched LDG.128 per thread (MLP=8) hide DRAM latency
// without relying on occupancy. x/out streamed with .cs (evict-first).
__global__ void __launch_bounds__(TPB) onetoone_sigmoid_k8_exact(
    const float4* __restrict__ x,
    const float4* __restrict__ w,
    const float4* __restrict__ b,
    float4* __restrict__ out)
{
    const int tid  = threadIdx.x;
    const int base = blockIdx.x * PER_BLOCK + tid;

    // Two distinct (w,b) pairs per thread; fold SCALE in once.
    float4 w0 = __ldg(&w[tid]);
    float4 b0 = __ldg(&b[tid]);
    float4 w1 = __ldg(&w[tid + TPB]);
    float4 b1 = __ldg(&b[tid + TPB]);
    w0.x *= SCALE; w0.y *= SCALE; w0.z *= SCALE; w0.w *= SCALE;
    b0.x *= SCALE; b0.y *= SCALE; b0.z *= SCALE; b0.w *= SCALE;
    w1.x *= SCALE; w1.y *= SCALE; w1.z *= SCALE; w1.w *= SCALE;
    b1.x *= SCALE; b1.y *= SCALE; b1.z *= SCALE; b1.w *= SCALE;

    // Front-batched independent loads (MLP_p1 = 8).
    float4 xv[UNROLL];
    #pragma unroll
    for (int u = 0; u < UNROLL; u++)
        xv[u] = __ldcs(&x[base + u * TPB]);

    #pragma unroll
    for (int u = 0; u < UNROLL; u++) {
        const float4 wv = (u & 1) ? w1 : w0;
        const float4 bv = (u & 1) ? b1 : b0;
        float4 r;
        float z;
        z = fmaf(xv[u].x, wv.x, bv.x);  r.x = 1.0f / (1.0f + __expf(-z));
        z = fmaf(xv[u].y, wv.y, bv.y);  r.y = 1.0f / (1.0f + __expf(-z));
        z = fmaf(xv[u].z, wv.z, bv.z);  r.z = 1.0f / (1.0f + __expf(-z));
        z = fmaf(xv[u].w, wv.w, bv.w);  r.w = 1.0f / (1.0f + __expf(-z));
        __stcs(&out[base + u * TPB], r);
    }
}

// Generic guarded fallback (only used if sizes ever change).
__global__ void __launch_bounds__(TPB) onetoone_sigmoid_generic(
    const float4* __restrict__ x,
    const float4* __restrict__ w,
    const float4* __restrict__ b,
    float4* __restrict__ out,
    int total4)
{
    int i = blockIdx.x * blockDim.x + threadIdx.x;
    if (i >= total4) return;
    int fi = i & (FEATURES / 4 - 1);
    float4 xv = __ldcs(&x[i]);
    float4 wv = __ldg(&w[fi]);
    float4 bv = __ldg(&b[fi]);
    float4 r;
    float z;
    z = SCALE * fmaf(xv.x, wv.x, bv.x);  r.x = 1.0f / (1.0f + __expf(-z));
    z = SCALE * fmaf(xv.y, wv.y, bv.y);  r.y = 1.0f / (1.0f + __expf(-z));
    z = SCALE * fmaf(xv.z, wv.z, bv.z);  r.z = 1.0f / (1.0f + __expf(-z));
    z = SCALE * fmaf(xv.w, wv.w, bv.w);  r.w = 1.0f / (1.0f + __expf(-z));
    __stcs(&out[i], r);
}

extern "C" void kernel_launch(void* const* d_in, const int* in_sizes, int n_in,
                              void* d_out, int out_size)
{
    const float4* x = (const float4*)d_in[0];   // input  [N, FEATURES] fp32
    const float4* w = (const float4*)d_in[1];   // weight [FEATURES]    fp32
    const float4* b = (const float4*)d_in[2];   // bias   [FEATURES]    fp32
    float4* out = (float4*)d_out;

    int total4 = out_size / 4;                  // 16,777,216
    if ((total4 % PER_BLOCK) == 0) {
        int blocks = total4 / PER_BLOCK;        // 8192
        onetoone_sigmoid_k8_exact<<<blocks, TPB>>>(x, w, b, out);
    } else {
        int blocks = (total4 + TPB - 1) / TPB;
        onetoone_sigmoid_generic<<<blocks, TPB>>>(x, w, b, out, total4);
    }
}